// round 7
// baseline (speedup 1.0000x reference)
#include <cuda_runtime.h>
#include <cuda_bf16.h>
#include <math.h>
#include <stdint.h>

#define TOLC   0.01f
#define ALPHAC 0.1f
#define SLOPEC 0.01f
#define EPSC   1e-10f

__device__ __forceinline__ float sr(float x)  { return x < 0.f ? 0.f : (x < 1.f ? 0.5f * x * x : x - 0.5f); }
__device__ __forceinline__ float srp(float x) { return x < 0.f ? 0.f : (x < 1.f ? x : 1.f); }
__device__ __forceinline__ float srp_out(float z) { return z <= 0.f ? 0.f : (z < 0.5f ? sqrtf(2.f * z) : 1.f); }
__device__ __forceinline__ float lrelu(float x) { return x >= 0.f ? x : SLOPEC * x; }

__device__ __forceinline__ uint32_t packbf(float v0, float v1) {
    uint32_t r; asm("cvt.rn.bf16x2.f32 %0, %1, %2;" : "=r"(r) : "f"(v1), "f"(v0)); return r;
}
__device__ __forceinline__ float bf16rt(float v) {
    return __bfloat162float(__float2bfloat16(v));
}
__device__ __forceinline__ uint32_t smem_u32(const void* p) {
    uint32_t a;
    asm("{ .reg .u64 t; cvta.to.shared.u64 t, %1; cvt.u32.u64 %0, t; }" : "=r"(a) : "l"(p));
    return a;
}
__device__ __forceinline__ void ldsm4(uint32_t* r, uint32_t addr) {
    asm volatile("ldmatrix.sync.aligned.m8n8.x4.shared.b16 {%0,%1,%2,%3}, [%4];"
                 : "=r"(r[0]), "=r"(r[1]), "=r"(r[2]), "=r"(r[3]) : "r"(addr));
}
__device__ __forceinline__ void mma_bf16(float* c,
                                         uint32_t a0, uint32_t a1, uint32_t a2, uint32_t a3,
                                         uint32_t b0, uint32_t b1) {
    asm volatile("mma.sync.aligned.m16n8k16.row.col.f32.bf16.bf16.f32 "
                 "{%0,%1,%2,%3}, {%4,%5,%6,%7}, {%8,%9}, {%0,%1,%2,%3};"
                 : "+f"(c[0]), "+f"(c[1]), "+f"(c[2]), "+f"(c[3])
                 : "r"(a0), "r"(a1), "r"(a2), "r"(a3), "r"(b0), "r"(b1));
}

// ============================================================================
// Fused kernel: per CTA of 128 points:
//   phase 1 (FMA pipe): ICNN V + VJP, two 64-point sub-passes -> smem gradV/V
//   phase 2 (tensor pipe): f_hat MLP via 2x-bf16 mma.sync + projection
// Co-resident CTAs desynchronize -> the two phases overlap across pipes.
// ============================================================================
constexpr int TB = 256;
constexpr int ZS = 65;                         // vnet padded stride
constexpr int ST = 136;                        // fhat bf16 row stride
constexpr int TILE_A = 128 * ST * 2;           // 34816 B
constexpr int TILE_W = 64 * ST * 2;            // 17408 B
constexpr int U_BYTES = 2 * TILE_A + 2 * TILE_W;   // 104448 (>= vnet 66560)
constexpr int MISC = U_BYTES;
// misc floats: sx[256] sgv[256] sVv[128] sb[128] sff[258] sp0[128] sp1[128] sd[128] sgf[64]
constexpr int MF_SX  = 0;
constexpr int MF_SGV = 256;
constexpr int MF_SVV = 512;
constexpr int MF_SB  = 640;
constexpr int MF_SFF = 768;
constexpr int MF_SP0 = 1026;
constexpr int MF_SP1 = 1154;
constexpr int MF_SD  = 1282;
constexpr int MF_SGF = 1410;
constexpr int MF_TOT = 1474;
constexpr int SMEM_BYTES = MISC + MF_TOT * 4;  // 110344 < 113664 -> 2 CTAs/SM

__global__ __launch_bounds__(TB, 2)
void icnn_fused(const float* __restrict__ X,   const float* __restrict__ Xs,
                const float* __restrict__ Vl1, const float* __restrict__ V2x,
                const float* __restrict__ V2z, const float* __restrict__ V3x,
                const float* __restrict__ V3z, const float* __restrict__ Vfx,
                const float* __restrict__ Vfz,
                const float* __restrict__ f1w, const float* __restrict__ f1b,
                const float* __restrict__ f2w, const float* __restrict__ f2b,
                const float* __restrict__ f3w, const float* __restrict__ f3b,
                const float* __restrict__ f4w, const float* __restrict__ f4b,
                const float* __restrict__ f5w, const float* __restrict__ f5b,
                const float* __restrict__ ffw, const float* __restrict__ ffb,
                float* __restrict__ out, int n)
{
    extern __shared__ __align__(16) char smb[];
    // vnet view of union region
    float* sz1 = (float*)smb;
    float* sz2 = sz1 + 64 * ZS;
    float* sz3 = sz1 + 128 * ZS;
    float* sW  = sz1 + 192 * ZS;
    // fhat view of union region
    __nv_bfloat16* Ahi = (__nv_bfloat16*)smb;
    __nv_bfloat16* Alo = (__nv_bfloat16*)(smb + TILE_A);
    __nv_bfloat16* Whi = (__nv_bfloat16*)(smb + 2 * TILE_A);
    __nv_bfloat16* Wlo = (__nv_bfloat16*)(smb + 2 * TILE_A + TILE_W);
    // misc
    float* mf  = (float*)(smb + MISC);
    float* sx  = mf + MF_SX;
    float* sgv = mf + MF_SGV;
    float* sVv = mf + MF_SVV;
    float* sb  = mf + MF_SB;
    float* sff = mf + MF_SFF;
    float* sp0 = mf + MF_SP0;
    float* sp1 = mf + MF_SP1;
    float* sd  = mf + MF_SD;
    float* sgf = mf + MF_SGF;

    const int t    = threadIdx.x;
    const int wid  = t >> 5;
    const int lane = t & 31;
    const int gid  = lane >> 2;
    const int tig  = lane & 3;
    const int r0   = wid * 16;
    const int base = blockIdx.x * 128;
    const int ty   = t >> 4;
    const int tx   = t & 15;

    // ---- stage X (128 points, clamped) + ff weights ----
    {
        int p = t >> 1, c = t & 1;
        int gi = base + p; if (gi >= n) gi = n - 1;
        sx[t] = X[gi * 2 + c];
    }
    for (int i = t; i < 258; i += TB) sff[i] = (i < 256) ? ffw[i] : ffb[i - 256];
    __syncthreads();

    // ========================================================================
    // Phase 1: V network (two 64-point sub-passes, SIMT fp32)
    // ========================================================================
    for (int sub = 0; sub < 2; sub++) {
        const int pbase = sub * 64;

        for (int i = t; i < 128; i += TB) {
            int gi = base + pbase + (i >> 1); if (gi >= n) gi = n - 1;
            sd[i] = sx[pbase * 2 + i] - Xs[gi * 2 + (i & 1)];
        }
        __syncthreads();

        for (int i = t; i < 64 * 64; i += TB) {
            int p = i >> 6, j = i & 63;
            float a = sd[p * 2] * Vl1[j * 2] + sd[p * 2 + 1] * Vl1[j * 2 + 1];
            sz1[p * ZS + j] = sr(a);
        }
        for (int i = t; i < 64 * 64; i += TB) sW[(i >> 6) * ZS + (i & 63)] = V2z[i];
        __syncthreads();

        {   // z2
            float acc[4][4];
            #pragma unroll
            for (int pi = 0; pi < 4; pi++) {
                int p = ty + 16 * pi;
                #pragma unroll
                for (int ji = 0; ji < 4; ji++) {
                    int j = tx + 16 * ji;
                    acc[pi][ji] = sd[p * 2] * V2x[j * 2] + sd[p * 2 + 1] * V2x[j * 2 + 1];
                }
            }
            #pragma unroll 4
            for (int k = 0; k < 64; k++) {
                float a[4], w[4];
                #pragma unroll
                for (int pi = 0; pi < 4; pi++) a[pi] = sz1[(ty + 16 * pi) * ZS + k];
                #pragma unroll
                for (int ji = 0; ji < 4; ji++) w[ji] = sW[(tx + 16 * ji) * ZS + k];
                #pragma unroll
                for (int pi = 0; pi < 4; pi++)
                    #pragma unroll
                    for (int ji = 0; ji < 4; ji++) acc[pi][ji] += a[pi] * w[ji];
            }
            #pragma unroll
            for (int pi = 0; pi < 4; pi++)
                #pragma unroll
                for (int ji = 0; ji < 4; ji++)
                    sz2[(ty + 16 * pi) * ZS + tx + 16 * ji] = sr(acc[pi][ji]);
        }
        __syncthreads();
        for (int i = t; i < 64 * 64; i += TB) sW[(i >> 6) * ZS + (i & 63)] = V3z[i];
        __syncthreads();

        {   // z3
            float acc[4][4];
            #pragma unroll
            for (int pi = 0; pi < 4; pi++) {
                int p = ty + 16 * pi;
                #pragma unroll
                for (int ji = 0; ji < 4; ji++) {
                    int j = tx + 16 * ji;
                    acc[pi][ji] = sd[p * 2] * V3x[j * 2] + sd[p * 2 + 1] * V3x[j * 2 + 1];
                }
            }
            #pragma unroll 4
            for (int k = 0; k < 64; k++) {
                float a[4], w[4];
                #pragma unroll
                for (int pi = 0; pi < 4; pi++) a[pi] = sz2[(ty + 16 * pi) * ZS + k];
                #pragma unroll
                for (int ji = 0; ji < 4; ji++) w[ji] = sW[(tx + 16 * ji) * ZS + k];
                #pragma unroll
                for (int pi = 0; pi < 4; pi++)
                    #pragma unroll
                    for (int ji = 0; ji < 4; ji++) acc[pi][ji] += a[pi] * w[ji];
            }
            #pragma unroll
            for (int pi = 0; pi < 4; pi++)
                #pragma unroll
                for (int ji = 0; ji < 4; ji++)
                    sz3[(ty + 16 * pi) * ZS + tx + 16 * ji] = sr(acc[pi][ji]);
        }
        __syncthreads();

        if (t < 64) {
            int p = t;
            float af = sd[p * 2] * Vfx[0] + sd[p * 2 + 1] * Vfx[1];
            #pragma unroll 4
            for (int k = 0; k < 64; k++) af += Vfz[k] * sz3[p * ZS + k];
            float zf = sr(af);
            sgf[p] = srp(zf) * srp(af);
            sVv[pbase + p] = sr(zf) + TOLC * (sd[p * 2] * sd[p * 2] + sd[p * 2 + 1] * sd[p * 2 + 1]);
        }
        __syncthreads();

        for (int i = t; i < 64 * 64; i += TB) {
            int p = i >> 6, j = i & 63;
            float z = sz3[p * ZS + j];
            sz3[p * ZS + j] = sgf[p] * Vfz[j] * srp_out(z);
        }
        __syncthreads();

        {   // g_a2 (sW holds V3z)
            float acc[4][4] = {};
            #pragma unroll 4
            for (int k = 0; k < 64; k++) {
                float a[4], w[4];
                #pragma unroll
                for (int pi = 0; pi < 4; pi++) a[pi] = sz3[(ty + 16 * pi) * ZS + k];
                #pragma unroll
                for (int ji = 0; ji < 4; ji++) w[ji] = sW[k * ZS + tx + 16 * ji];
                #pragma unroll
                for (int pi = 0; pi < 4; pi++)
                    #pragma unroll
                    for (int ji = 0; ji < 4; ji++) acc[pi][ji] += a[pi] * w[ji];
            }
            #pragma unroll
            for (int pi = 0; pi < 4; pi++)
                #pragma unroll
                for (int ji = 0; ji < 4; ji++) {
                    int p = ty + 16 * pi, j = tx + 16 * ji;
                    float z = sz2[p * ZS + j];
                    sz2[p * ZS + j] = acc[pi][ji] * srp_out(z);
                }
        }
        __syncthreads();
        for (int i = t; i < 64 * 64; i += TB) sW[(i >> 6) * ZS + (i & 63)] = V2z[i];
        __syncthreads();

        {   // g_a1
            float acc[4][4] = {};
            #pragma unroll 4
            for (int k = 0; k < 64; k++) {
                float a[4], w[4];
                #pragma unroll
                for (int pi = 0; pi < 4; pi++) a[pi] = sz2[(ty + 16 * pi) * ZS + k];
                #pragma unroll
                for (int ji = 0; ji < 4; ji++) w[ji] = sW[k * ZS + tx + 16 * ji];
                #pragma unroll
                for (int pi = 0; pi < 4; pi++)
                    #pragma unroll
                    for (int ji = 0; ji < 4; ji++) acc[pi][ji] += a[pi] * w[ji];
            }
            #pragma unroll
            for (int pi = 0; pi < 4; pi++)
                #pragma unroll
                for (int ji = 0; ji < 4; ji++) {
                    int p = ty + 16 * pi, j = tx + 16 * ji;
                    float z = sz1[p * ZS + j];
                    sz1[p * ZS + j] = acc[pi][ji] * srp_out(z);
                }
        }
        __syncthreads();

        if (t < 128) {
            int p = t >> 1, c = t & 1;
            float acc = sgf[p] * Vfx[c] + 2.f * TOLC * sd[p * 2 + c];
            #pragma unroll 4
            for (int k = 0; k < 64; k++) {
                acc += sz3[p * ZS + k] * V3x[k * 2 + c];
                acc += sz2[p * ZS + k] * V2x[k * 2 + c];
                acc += sz1[p * ZS + k] * Vl1[k * 2 + c];
            }
            sgv[(pbase + p) * 2 + c] = acc;
        }
        __syncthreads();
    }

    // ========================================================================
    // Phase 2: f_hat MLP (2x-bf16 mma.sync) + projection
    // ========================================================================
    // ldmatrix per-lane base byte offsets
    const int aRow = r0 + (lane & 7) + ((lane >> 3) & 1) * 8;
    const int aCol = ((lane >> 4) & 1) * 8;
    const uint32_t aOff = (uint32_t)(aRow * ST + aCol) * 2;
    const int bRow = (lane & 7) + ((lane >> 4) & 1) * 8;
    const int bCol = ((lane >> 3) & 1) * 8;
    const uint32_t bOff = (uint32_t)(bRow * ST + bCol) * 2;

    const uint32_t aHiB = smem_u32(Ahi) + aOff;
    const uint32_t aLoB = smem_u32(Alo) + aOff;
    const uint32_t wHiB = smem_u32(Whi) + bOff;
    const uint32_t wLoB = smem_u32(Wlo) + bOff;

    // ---- layer 1 (K=2, SIMT) -> A hi/lo ----
    for (int i = t; i < 128 * 128; i += TB) {
        int p = i >> 7, j = i & 127;
        float v  = lrelu(sx[2 * p] * f1w[2 * j] + sx[2 * p + 1] * f1w[2 * j + 1] + f1b[j]);
        float h  = bf16rt(v);
        Ahi[p * ST + j] = __float2bfloat16(v);
        Alo[p * ST + j] = __float2bfloat16(v - h);
    }
    __syncthreads();

    const float* Ws[4] = { f2w, f3w, f4w, f5w };
    const float* Bs[4] = { f2b, f3b, f4b, f5b };

    for (int L = 0; L < 4; L++) {
        const float* Wg = Ws[L];
        float acc[16][4];
        #pragma unroll
        for (int q = 0; q < 16; q++)
            #pragma unroll
            for (int c = 0; c < 4; c++) acc[q][c] = 0.f;

        #pragma unroll 1
        for (int half = 0; half < 2; half++) {
            for (int i = t; i < 64 * 32; i += TB) {
                int j  = i >> 5;
                int k4 = (i & 31) << 2;
                float4 w = *(const float4*)(Wg + (half * 64 + j) * 128 + k4);
                float h0 = bf16rt(w.x), h1 = bf16rt(w.y), h2 = bf16rt(w.z), h3 = bf16rt(w.w);
                *(uint2*)(Whi + j * ST + k4) = make_uint2(packbf(w.x, w.y), packbf(w.z, w.w));
                *(uint2*)(Wlo + j * ST + k4) =
                    make_uint2(packbf(w.x - h0, w.y - h1), packbf(w.z - h2, w.w - h3));
            }
            if (half == 0 && t < 128) sb[t] = Bs[L][t];
            __syncthreads();

            #pragma unroll
            for (int kt = 0; kt < 8; kt++) {
                const uint32_t kb = kt * 32;
                uint32_t ah[4], al[4];
                ldsm4(ah, aHiB + kb);
                ldsm4(al, aLoB + kb);
                #pragma unroll
                for (int p = 0; p < 4; p++) {
                    uint32_t bh[4], bl[4];
                    const uint32_t po = (uint32_t)(p * 16 * ST * 2) + kb;
                    ldsm4(bh, wHiB + po);
                    ldsm4(bl, wLoB + po);
                    float* c0 = acc[half * 8 + 2 * p];
                    float* c1 = acc[half * 8 + 2 * p + 1];
                    mma_bf16(c0, ah[0], ah[1], ah[2], ah[3], bh[0], bh[1]);
                    mma_bf16(c0, ah[0], ah[1], ah[2], ah[3], bl[0], bl[1]);
                    mma_bf16(c0, al[0], al[1], al[2], al[3], bh[0], bh[1]);
                    mma_bf16(c1, ah[0], ah[1], ah[2], ah[3], bh[2], bh[3]);
                    mma_bf16(c1, ah[0], ah[1], ah[2], ah[3], bl[2], bl[3]);
                    mma_bf16(c1, al[0], al[1], al[2], al[3], bh[2], bh[3]);
                }
            }
            __syncthreads();
        }

        if (L < 3) {
            #pragma unroll
            for (int q = 0; q < 16; q++) {
                int c = (q >> 3) * 64 + (q & 7) * 8 + 2 * tig;
                float v0 = lrelu(acc[q][0] + sb[c]);
                float v1 = lrelu(acc[q][1] + sb[c + 1]);
                float v2 = lrelu(acc[q][2] + sb[c]);
                float v3 = lrelu(acc[q][3] + sb[c + 1]);
                float h0 = bf16rt(v0), h1 = bf16rt(v1), h2 = bf16rt(v2), h3 = bf16rt(v3);
                *(uint32_t*)(Ahi + (r0 + gid) * ST + c)     = packbf(v0, v1);
                *(uint32_t*)(Ahi + (r0 + gid + 8) * ST + c) = packbf(v2, v3);
                *(uint32_t*)(Alo + (r0 + gid) * ST + c)     = packbf(v0 - h0, v1 - h1);
                *(uint32_t*)(Alo + (r0 + gid + 8) * ST + c) = packbf(v2 - h2, v3 - h3);
            }
            __syncthreads();
        } else {
            float p0 = 0.f, p1 = 0.f, q0 = 0.f, q1 = 0.f;
            #pragma unroll
            for (int q = 0; q < 16; q++) {
                int c = (q >> 3) * 64 + (q & 7) * 8 + 2 * tig;
                float v0 = lrelu(acc[q][0] + sb[c]);
                float v1 = lrelu(acc[q][1] + sb[c + 1]);
                float v2 = lrelu(acc[q][2] + sb[c]);
                float v3 = lrelu(acc[q][3] + sb[c + 1]);
                p0 = fmaf(v0, sff[c], fmaf(v1, sff[c + 1], p0));
                p1 = fmaf(v0, sff[128 + c], fmaf(v1, sff[129 + c], p1));
                q0 = fmaf(v2, sff[c], fmaf(v3, sff[c + 1], q0));
                q1 = fmaf(v2, sff[128 + c], fmaf(v3, sff[129 + c], q1));
            }
            #pragma unroll
            for (int m = 1; m < 4; m <<= 1) {
                p0 += __shfl_xor_sync(0xFFFFFFFFu, p0, m);
                p1 += __shfl_xor_sync(0xFFFFFFFFu, p1, m);
                q0 += __shfl_xor_sync(0xFFFFFFFFu, q0, m);
                q1 += __shfl_xor_sync(0xFFFFFFFFu, q1, m);
            }
            if (tig == 0) {
                sp0[r0 + gid] = p0;  sp1[r0 + gid] = p1;
                sp0[r0 + gid + 8] = q0;  sp1[r0 + gid + 8] = q1;
            }
            __syncthreads();
        }
    }

    // ---- final projection (gradV/V from smem) ----
    if (t < 128) {
        int gi = base + t;
        if (gi < n) {
            float fh0 = sff[256] + sp0[t];
            float fh1 = sff[257] + sp1[t];
            float g0 = sgv[2 * t], g1 = sgv[2 * t + 1];
            float V  = sVv[t];
            float vn  = g0 * g0 + g1 * g1;
            float num = fh0 * g0 + fh1 * g1 + ALPHAC * V;
            float fm  = (num > 0.f ? num : 0.f) / (vn + EPSC);
            out[2 * gi]     = fh0 - g0 * fm;
            out[2 * gi + 1] = fh1 - g1 * fm;
        }
    }
}

// ============================================================================
extern "C" void kernel_launch(void* const* d_in, const int* in_sizes, int n_in,
                              void* d_out, int out_size)
{
    const float* X   = (const float*)d_in[0];
    const float* Xs  = (const float*)d_in[1];
    const float* Vl1 = (const float*)d_in[2];
    const float* V2x = (const float*)d_in[3];
    const float* V2z = (const float*)d_in[4];
    const float* V3x = (const float*)d_in[5];
    const float* V3z = (const float*)d_in[6];
    const float* Vfx = (const float*)d_in[7];
    const float* Vfz = (const float*)d_in[8];
    const float* f1w = (const float*)d_in[9];
    const float* f1b = (const float*)d_in[10];
    const float* f2w = (const float*)d_in[11];
    const float* f2b = (const float*)d_in[12];
    const float* f3w = (const float*)d_in[13];
    const float* f3b = (const float*)d_in[14];
    const float* f4w = (const float*)d_in[15];
    const float* f4b = (const float*)d_in[16];
    const float* f5w = (const float*)d_in[17];
    const float* f5b = (const float*)d_in[18];
    const float* ffw = (const float*)d_in[19];
    const float* ffb = (const float*)d_in[20];

    int n = in_sizes[0] / 2;

    cudaFuncSetAttribute(icnn_fused, cudaFuncAttributeMaxDynamicSharedMemorySize, SMEM_BYTES);

    icnn_fused<<<(n + 127) / 128, TB, SMEM_BYTES>>>(
        X, Xs, Vl1, V2x, V2z, V3x, V3z, Vfx, Vfz,
        f1w, f1b, f2w, f2b, f3w, f3b, f4w, f4b, f5w, f5b, ffw, ffb,
        (float*)d_out, n);
}